// round 1
// baseline (speedup 1.0000x reference)
#include <cuda_runtime.h>
#include <math.h>

#define BATCH   512
#define STEPS   128
#define TSTEPS  255          // 127 history + 128 action
#define DIN     256
#define UDIM    256
#define G4      1024         // 4*UDIM

// Scratch (static device allocations — no cudaMalloc anywhere)
__device__ float g_state[BATCH * UDIM];
__device__ float g_h[BATCH * UDIM];
__device__ float g_G[(size_t)TSTEPS * BATCH * G4];   // 535 MB: x@Wk + bl, [t][b][4U]

// ---------------------------------------------------------------------------
// K1: preamble — ms/rs/re/im + combine -> state [512,256]
// one block per batch row, 256 threads
// ---------------------------------------------------------------------------
__global__ void __launch_bounds__(256) preamble_kernel(
    const float* __restrict__ motion, const float* __restrict__ robot,
    const float* __restrict__ osr,    const float* __restrict__ osi,
    const float* __restrict__ orr_,   const float* __restrict__ ori_,
    const float* __restrict__ Wm, const float* __restrict__ bm,
    const float* __restrict__ Wr, const float* __restrict__ br,
    const float* __restrict__ Wre, const float* __restrict__ bre,
    const float* __restrict__ Wim, const float* __restrict__ bim,
    const float* __restrict__ Wc,  const float* __restrict__ bc)
{
    __shared__ float comb[768];
    const int row = blockIdx.x;
    const int n   = threadIdx.x;

    // ms = relu(motion @ Wm + bm)   [64 -> 256]
    float s = bm[n];
    #pragma unroll 8
    for (int k = 0; k < 64; k++) s += motion[row*64 + k] * Wm[k*256 + n];
    comb[n] = fmaxf(s, 0.f);

    // rs = relu(robot @ Wr + br)    [128 -> 256]
    s = br[n];
    #pragma unroll 8
    for (int k = 0; k < 128; k++) s += robot[row*128 + k] * Wr[k*256 + n];
    comb[256 + n] = fmaxf(s, 0.f);

    if (n < 128) {
        // re = relu(concat(osc_state_real, osc_real) @ Wre + bre) [128 -> 128]
        float s3 = bre[n];
        #pragma unroll 8
        for (int k = 0; k < 64; k++) s3 += osr [row*64 + k] * Wre[k*128 + n];
        #pragma unroll 8
        for (int k = 0; k < 64; k++) s3 += orr_[row*64 + k] * Wre[(64+k)*128 + n];
        comb[512 + n] = fmaxf(s3, 0.f);
    } else {
        const int m = n - 128;
        float s4 = bim[m];
        #pragma unroll 8
        for (int k = 0; k < 64; k++) s4 += osi [row*64 + k] * Wim[k*128 + m];
        #pragma unroll 8
        for (int k = 0; k < 64; k++) s4 += ori_[row*64 + k] * Wim[(64+k)*128 + m];
        comb[640 + m] = fmaxf(s4, 0.f);
    }
    __syncthreads();

    // state = relu(comb @ Wc + bc)  [768 -> 256]
    float s5 = bc[n];
    #pragma unroll 8
    for (int k = 0; k < 768; k++) s5 += comb[k] * Wc[k*256 + n];
    g_state[row*256 + n] = fmaxf(s5, 0.f);
}

// ---------------------------------------------------------------------------
// K2: G[t,b,:] = x_{t,b} @ Wk + bl  for all 255 steps.
// Tiled fp32 GEMM, M=255*512=130560 (m = t*512 + b), K=256, N=1024.
// 64x64 tile, 256 threads, 4x4 microtile, BK=16.
// ---------------------------------------------------------------------------
__global__ void __launch_bounds__(256) xwk_kernel(
    const float* __restrict__ hist, const float* __restrict__ act,
    const float* __restrict__ Wk,   const float* __restrict__ bl)
{
    __shared__ float As[16][68];   // [k][row], padded; float4-aligned reads
    __shared__ float Bs[16][64];   // [k][col]

    const int tid = threadIdx.x;
    const int tx  = tid & 15, ty = tid >> 4;
    const int bm0 = blockIdx.y * 64;
    const int bn0 = blockIdx.x * 64;

    // A-load mapping: one float4 of one row per thread per stage
    const int ar = tid >> 2;           // tile row 0..63
    const int ac = (tid & 3) * 4;      // k offset 0,4,8,12
    {
        // compute source row pointer for m = bm0 + ar
    }
    const int m = bm0 + ar;
    const int t = m >> 9;
    const int b = m & 511;
    const float* arow = (t < 127)
        ? (hist + ((size_t)b * STEPS + t) * DIN)
        : (act  + ((size_t)b * STEPS + (t - 127)) * DIN);

    // B-load mapping
    const int brr = tid >> 4;          // k row 0..15
    const int bcc = (tid & 15) * 4;    // col 0..60

    float acc[4][4] = {};

    for (int k0 = 0; k0 < 256; k0 += 16) {
        float4 av = *(const float4*)(arow + k0 + ac);
        As[ac+0][ar] = av.x; As[ac+1][ar] = av.y;
        As[ac+2][ar] = av.z; As[ac+3][ar] = av.w;
        *(float4*)&Bs[brr][bcc] =
            *(const float4*)(Wk + (size_t)(k0 + brr) * G4 + bn0 + bcc);
        __syncthreads();

        #pragma unroll
        for (int k = 0; k < 16; k++) {
            float4 a4 = *(const float4*)&As[k][ty*4];
            float4 b4 = *(const float4*)&Bs[k][tx*4];
            float a[4] = {a4.x, a4.y, a4.z, a4.w};
            float bb[4] = {b4.x, b4.y, b4.z, b4.w};
            #pragma unroll
            for (int i = 0; i < 4; i++)
                #pragma unroll
                for (int j = 0; j < 4; j++)
                    acc[i][j] += a[i] * bb[j];
        }
        __syncthreads();
    }

    #pragma unroll
    for (int i = 0; i < 4; i++) {
        const int gm = bm0 + ty*4 + i;
        #pragma unroll
        for (int j = 0; j < 4; j++) {
            const int gn = bn0 + tx*4 + j;
            g_G[(size_t)gm * G4 + gn] = acc[i][j] + bl[gn];
        }
    }
}

// ---------------------------------------------------------------------------
// K3: persistent LSTM recurrence. 128 CTAs x 4 batch rows, 256 threads.
// Thread n owns gate feature n (gates at offsets n, 256+n, 512+n, 768+n),
// so the c/h update is thread-local; h is rebroadcast via smem each step.
// No cross-CTA traffic (batch-partitioned).
// ---------------------------------------------------------------------------
__global__ void __launch_bounds__(256, 1) recur_kernel(const float* __restrict__ Wrk)
{
    __shared__ float hs[4][256];
    const int n  = threadIdx.x;
    const int r0 = blockIdx.x * 4;

    float c[4];
    #pragma unroll
    for (int r = 0; r < 4; r++) {
        c[r] = g_state[(r0 + r) * 256 + n];
        hs[r][n] = c[r];
    }
    __syncthreads();

    const float* wp0 = Wrk + n;

    for (int tstep = 0; tstep < TSTEPS; tstep++) {
        float acc[16];
        #pragma unroll
        for (int i = 0; i < 16; i++) acc[i] = 0.f;

        #pragma unroll 4
        for (int k = 0; k < 256; k++) {
            const float h0 = hs[0][k], h1 = hs[1][k], h2 = hs[2][k], h3 = hs[3][k];
            const float* wp = wp0 + k * G4;
            const float wi = wp[0], wf = wp[256], wg = wp[512], wo = wp[768];
            acc[0]  += wi*h0; acc[1]  += wi*h1; acc[2]  += wi*h2; acc[3]  += wi*h3;
            acc[4]  += wf*h0; acc[5]  += wf*h1; acc[6]  += wf*h2; acc[7]  += wf*h3;
            acc[8]  += wg*h0; acc[9]  += wg*h1; acc[10] += wg*h2; acc[11] += wg*h3;
            acc[12] += wo*h0; acc[13] += wo*h1; acc[14] += wo*h2; acc[15] += wo*h3;
        }

        const float* Gp = g_G + ((size_t)tstep * BATCH + r0) * G4 + n;
        float hn[4];
        #pragma unroll
        for (int r = 0; r < 4; r++) {
            const float zi = acc[r]      + Gp[r*G4];
            const float zf = acc[4 + r]  + Gp[r*G4 + 256];
            const float zg = acc[8 + r]  + Gp[r*G4 + 512];
            const float zo = acc[12 + r] + Gp[r*G4 + 768];
            const float ig = 1.f / (1.f + expf(-zi));
            const float fg = 1.f / (1.f + expf(-zf));
            const float gg = tanhf(zg);
            const float og = 1.f / (1.f + expf(-zo));
            c[r] = fg * c[r] + ig * gg;
            hn[r] = og * tanhf(c[r]);
        }

        __syncthreads();   // all reads of old h done
        #pragma unroll
        for (int r = 0; r < 4; r++) hs[r][n] = hn[r];
        __syncthreads();   // new h visible
    }

    #pragma unroll
    for (int r = 0; r < 4; r++) g_h[(r0 + r) * 256 + n] = hs[r][n];
}

// ---------------------------------------------------------------------------
// K4: out = relu(h @ Wo + bo), [512,1]. One warp per batch row.
// ---------------------------------------------------------------------------
__global__ void out_kernel(const float* __restrict__ Wo,
                           const float* __restrict__ bo,
                           float* __restrict__ out)
{
    const int b = blockIdx.x;
    const int lane = threadIdx.x;
    float s = 0.f;
    #pragma unroll
    for (int k = lane; k < 256; k += 32) s += g_h[b*256 + k] * Wo[k];
    #pragma unroll
    for (int off = 16; off; off >>= 1) s += __shfl_down_sync(0xffffffffu, s, off);
    if (lane == 0) out[b] = fmaxf(s + bo[0], 0.f);
}

// ---------------------------------------------------------------------------
extern "C" void kernel_launch(void* const* d_in, const int* in_sizes, int n_in,
                              void* d_out, int out_size)
{
    const float* motion = (const float*)d_in[0];
    const float* robot  = (const float*)d_in[1];
    const float* osr    = (const float*)d_in[2];
    const float* osi    = (const float*)d_in[3];
    const float* hist   = (const float*)d_in[4];
    const float* act    = (const float*)d_in[5];
    const float* orr_   = (const float*)d_in[6];
    const float* ori_   = (const float*)d_in[7];
    const float* Wm  = (const float*)d_in[8];
    const float* bm  = (const float*)d_in[9];
    const float* Wr  = (const float*)d_in[10];
    const float* br  = (const float*)d_in[11];
    const float* Wre = (const float*)d_in[12];
    const float* bre = (const float*)d_in[13];
    const float* Wim = (const float*)d_in[14];
    const float* bim = (const float*)d_in[15];
    const float* Wc  = (const float*)d_in[16];
    const float* bc  = (const float*)d_in[17];
    const float* Wk  = (const float*)d_in[18];
    const float* Wrk = (const float*)d_in[19];
    const float* bl  = (const float*)d_in[20];
    const float* Wo  = (const float*)d_in[21];
    const float* bo  = (const float*)d_in[22];
    float* out = (float*)d_out;

    preamble_kernel<<<BATCH, 256>>>(motion, robot, osr, osi, orr_, ori_,
                                    Wm, bm, Wr, br, Wre, bre, Wim, bim, Wc, bc);

    dim3 g2(G4 / 64, (TSTEPS * BATCH) / 64);   // (16, 2040)
    xwk_kernel<<<g2, 256>>>(hist, act, Wk, bl);

    recur_kernel<<<BATCH / 4 / 1, 256>>>(Wrk);  // 128 CTAs x 4 rows

    out_kernel<<<BATCH, 32>>>(Wo, bo, out);
}

// round 2
// speedup vs baseline: 1.4819x; 1.4819x over previous
#include <cuda_runtime.h>
#include <math.h>

#define BATCH   512
#define STEPS   128
#define TSTEPS  255          // 127 history + 128 action
#define DIN     256
#define UDIM    256
#define G4      1024         // 4*UDIM
#define RROWS   6            // batch rows per recurrence CTA
#define RCTAS   ((BATCH + RROWS - 1) / RROWS)   // 86

// Scratch (static device allocations — no cudaMalloc anywhere)
__device__ float  g_state[BATCH * UDIM];
__device__ float  g_h[BATCH * UDIM];
__device__ float  g_G[(size_t)TSTEPS * BATCH * G4];   // 535 MB: x@Wk + bl, [t][b][4U]
__device__ float4 g_W4[256 * 256];                    // Wrk reformat: (wi,wf,wg,wo) per (k,n)

// ---------------------------------------------------------------------------
// f32x2 packed-FMA helpers (sm_103a FFMA2 — only reachable via PTX)
// ---------------------------------------------------------------------------
union F2U { float2 f; unsigned long long u; };
union F4U { float4 f; ulonglong2 u; };

__device__ __forceinline__ void fma2(unsigned long long& d,
                                     unsigned long long a,
                                     unsigned long long b)
{
    asm("fma.rn.f32x2 %0, %1, %2, %0;" : "+l"(d) : "l"(a), "l"(b));
}
__device__ __forceinline__ unsigned long long dup2(float x)
{
    F2U t; t.f = make_float2(x, x); return t.u;
}
__device__ __forceinline__ float tanha(float x)
{
    float y; asm("tanh.approx.f32 %0, %1;" : "=f"(y) : "f"(x)); return y;
}
__device__ __forceinline__ float sigm(float x)
{
    return fmaf(0.5f, tanha(0.5f * x), 0.5f);
}

// ---------------------------------------------------------------------------
// K0: reformat Wrk [256,1024] -> W4[k][n] = (W[k][n], W[k][256+n], W[k][512+n], W[k][768+n])
// ---------------------------------------------------------------------------
__global__ void reformat_wrk(const float* __restrict__ Wrk)
{
    const int idx = blockIdx.x * 256 + threadIdx.x;   // 65536
    const int k = idx >> 8, n = idx & 255;
    const float* w = Wrk + k * G4 + n;
    g_W4[idx] = make_float4(w[0], w[256], w[512], w[768]);
}

// ---------------------------------------------------------------------------
// K1: preamble — ms/rs/re/im + combine -> state [512,256]
// ---------------------------------------------------------------------------
__global__ void __launch_bounds__(256) preamble_kernel(
    const float* __restrict__ motion, const float* __restrict__ robot,
    const float* __restrict__ osr,    const float* __restrict__ osi,
    const float* __restrict__ orr_,   const float* __restrict__ ori_,
    const float* __restrict__ Wm, const float* __restrict__ bm,
    const float* __restrict__ Wr, const float* __restrict__ br,
    const float* __restrict__ Wre, const float* __restrict__ bre,
    const float* __restrict__ Wim, const float* __restrict__ bim,
    const float* __restrict__ Wc,  const float* __restrict__ bc)
{
    __shared__ float comb[768];
    const int row = blockIdx.x;
    const int n   = threadIdx.x;

    float s = bm[n];
    #pragma unroll 8
    for (int k = 0; k < 64; k++) s += motion[row*64 + k] * Wm[k*256 + n];
    comb[n] = fmaxf(s, 0.f);

    s = br[n];
    #pragma unroll 8
    for (int k = 0; k < 128; k++) s += robot[row*128 + k] * Wr[k*256 + n];
    comb[256 + n] = fmaxf(s, 0.f);

    if (n < 128) {
        float s3 = bre[n];
        #pragma unroll 8
        for (int k = 0; k < 64; k++) s3 += osr [row*64 + k] * Wre[k*128 + n];
        #pragma unroll 8
        for (int k = 0; k < 64; k++) s3 += orr_[row*64 + k] * Wre[(64+k)*128 + n];
        comb[512 + n] = fmaxf(s3, 0.f);
    } else {
        const int m = n - 128;
        float s4 = bim[m];
        #pragma unroll 8
        for (int k = 0; k < 64; k++) s4 += osi [row*64 + k] * Wim[k*128 + m];
        #pragma unroll 8
        for (int k = 0; k < 64; k++) s4 += ori_[row*64 + k] * Wim[(64+k)*128 + m];
        comb[640 + m] = fmaxf(s4, 0.f);
    }
    __syncthreads();

    float s5 = bc[n];
    #pragma unroll 8
    for (int k = 0; k < 768; k++) s5 += comb[k] * Wc[k*256 + n];
    g_state[row*256 + n] = fmaxf(s5, 0.f);
}

// ---------------------------------------------------------------------------
// K2: G = x @ Wk + bl.  M=130560, K=256, N=1024.
// 128x128 tile, BK=16, 256 threads, 8x8 microtile, FFMA2, reg-prefetch.
// ---------------------------------------------------------------------------
__global__ void __launch_bounds__(256, 1) xwk_kernel(
    const float* __restrict__ hist, const float* __restrict__ act,
    const float* __restrict__ Wk,   const float* __restrict__ bl)
{
    __shared__ float As[16][132];   // [k][m], padded (2-way STS conflict max)
    __shared__ float Bs[16][128];   // [k][n]

    const int tid = threadIdx.x;
    const int tx  = tid & 15, ty = tid >> 4;
    const int bm0 = blockIdx.y * 128;
    const int bn0 = blockIdx.x * 128;

    // A loader: 2 float4 per thread (rows ra, ra+64)
    const int ra = tid >> 2;              // 0..63
    const int kc = (tid & 3) * 4;         // 0,4,8,12
    const int mA0 = bm0 + ra, mA1 = bm0 + ra + 64;
    const int tA0 = mA0 >> 9, bA0 = mA0 & 511;
    const int tA1 = mA1 >> 9, bA1 = mA1 & 511;
    const float* arow0 = (tA0 < 127)
        ? (hist + ((size_t)bA0 * STEPS + tA0) * DIN)
        : (act  + ((size_t)bA0 * STEPS + (tA0 - 127)) * DIN);
    const float* arow1 = (tA1 < 127)
        ? (hist + ((size_t)bA1 * STEPS + tA1) * DIN)
        : (act  + ((size_t)bA1 * STEPS + (tA1 - 127)) * DIN);

    // B loader: 2 float4 per thread (cols nb, nb+64), k row kb
    const int kb = tid >> 4;              // 0..15
    const int nb = (tid & 15) * 4;        // 0..60
    const float* bsrc = Wk + (size_t)kb * G4 + bn0 + nb;

    unsigned long long acc[8][4];
    #pragma unroll
    for (int i = 0; i < 8; i++)
        #pragma unroll
        for (int j = 0; j < 4; j++) acc[i][j] = 0ull;

    float4 a0 = *(const float4*)(arow0 + kc);
    float4 a1 = *(const float4*)(arow1 + kc);
    float4 b0 = *(const float4*)(bsrc);
    float4 b1 = *(const float4*)(bsrc + 64);

    for (int k0 = 0; k0 < 256; k0 += 16) {
        __syncthreads();   // previous compute done
        As[kc+0][ra] = a0.x; As[kc+1][ra] = a0.y; As[kc+2][ra] = a0.z; As[kc+3][ra] = a0.w;
        As[kc+0][ra+64] = a1.x; As[kc+1][ra+64] = a1.y; As[kc+2][ra+64] = a1.z; As[kc+3][ra+64] = a1.w;
        *(float4*)&Bs[kb][nb]      = b0;
        *(float4*)&Bs[kb][nb + 64] = b1;
        __syncthreads();

        if (k0 + 16 < 256) {
            a0 = *(const float4*)(arow0 + k0 + 16 + kc);
            a1 = *(const float4*)(arow1 + k0 + 16 + kc);
            b0 = *(const float4*)(bsrc + (size_t)(k0 + 16) * G4);
            b1 = *(const float4*)(bsrc + (size_t)(k0 + 16) * G4 + 64);
        }

        #pragma unroll
        for (int k = 0; k < 16; k++) {
            float4 av0 = *(const float4*)&As[k][ty*8];
            float4 av1 = *(const float4*)&As[k][ty*8 + 4];
            F4U bv0, bv1;
            bv0.f = *(const float4*)&Bs[k][tx*8];
            bv1.f = *(const float4*)&Bs[k][tx*8 + 4];
            unsigned long long bp[4] = { bv0.u.x, bv0.u.y, bv1.u.x, bv1.u.y };
            float afl[8] = { av0.x, av0.y, av0.z, av0.w, av1.x, av1.y, av1.z, av1.w };
            #pragma unroll
            for (int i = 0; i < 8; i++) {
                unsigned long long ad = dup2(afl[i]);
                #pragma unroll
                for (int j = 0; j < 4; j++) fma2(acc[i][j], ad, bp[j]);
            }
        }
    }

    // epilogue: +bl, store 2x STG.128 per row
    float blv[8];
    #pragma unroll
    for (int j = 0; j < 8; j++) blv[j] = bl[bn0 + tx*8 + j];

    #pragma unroll
    for (int i = 0; i < 8; i++) {
        const int m = bm0 + ty*8 + i;
        float v[8];
        #pragma unroll
        for (int j = 0; j < 4; j++) {
            F2U e; e.u = acc[i][j];
            v[j*2]   = e.f.x + blv[j*2];
            v[j*2+1] = e.f.y + blv[j*2+1];
        }
        float* dst = g_G + (size_t)m * G4 + bn0 + tx*8;
        *(float4*)dst       = make_float4(v[0], v[1], v[2], v[3]);
        *(float4*)(dst + 4) = make_float4(v[4], v[5], v[6], v[7]);
    }
}

// ---------------------------------------------------------------------------
// K3: persistent LSTM recurrence. 86 CTAs x 6 batch rows, 256 threads.
// W4 gate-interleaved float4 -> 1 LDG.128 per (k); h duplicated in smem
// (float2) so LDS.64 yields a packed FFMA2 operand directly.
// ---------------------------------------------------------------------------
__global__ void __launch_bounds__(256, 1) recur_kernel()
{
    __shared__ float2 hs2[RROWS][256];
    const int n  = threadIdx.x;
    const int r0 = blockIdx.x * RROWS;

    float c[RROWS];
    int gr[RROWS];
    #pragma unroll
    for (int r = 0; r < RROWS; r++) {
        gr[r] = min(r0 + r, BATCH - 1);        // clamp; dup rows recompute row 511
        c[r]  = g_state[gr[r] * 256 + n];
        hs2[r][n] = make_float2(c[r], c[r]);
    }
    __syncthreads();

    float hn[RROWS];
    for (int t = 0; t < TSTEPS; t++) {
        unsigned long long accif[RROWS], accgo[RROWS];
        #pragma unroll
        for (int r = 0; r < RROWS; r++) { accif[r] = 0ull; accgo[r] = 0ull; }

        const float4* wp = g_W4 + n;
        #pragma unroll 8
        for (int k = 0; k < 256; k++) {
            F4U w; w.f = wp[(size_t)k * 256];
            #pragma unroll
            for (int r = 0; r < RROWS; r++) {
                F2U hh; hh.f = hs2[r][k];
                fma2(accif[r], w.u.x, hh.u);
                fma2(accgo[r], w.u.y, hh.u);
            }
        }

        #pragma unroll
        for (int r = 0; r < RROWS; r++) {
            const float* Gp = g_G + ((size_t)t * BATCH + gr[r]) * G4 + n;
            F2U eif, ego; eif.u = accif[r]; ego.u = accgo[r];
            const float zi = eif.f.x + Gp[0];
            const float zf = eif.f.y + Gp[256];
            const float zg = ego.f.x + Gp[512];
            const float zo = ego.f.y + Gp[768];
            const float ig = sigm(zi);
            const float fg = sigm(zf);
            const float gg = tanha(zg);
            const float og = sigm(zo);
            c[r]  = fg * c[r] + ig * gg;
            hn[r] = og * tanha(c[r]);
        }

        __syncthreads();   // all reads of old h done
        #pragma unroll
        for (int r = 0; r < RROWS; r++) hs2[r][n] = make_float2(hn[r], hn[r]);
        __syncthreads();   // new h visible
    }

    #pragma unroll
    for (int r = 0; r < RROWS; r++)
        if (r0 + r < BATCH) g_h[(r0 + r) * 256 + n] = hn[r];
}

// ---------------------------------------------------------------------------
// K4: out = relu(h @ Wo + bo), [512,1]. One warp per batch row.
// ---------------------------------------------------------------------------
__global__ void out_kernel(const float* __restrict__ Wo,
                           const float* __restrict__ bo,
                           float* __restrict__ out)
{
    const int b = blockIdx.x;
    const int lane = threadIdx.x;
    float s = 0.f;
    #pragma unroll
    for (int k = lane; k < 256; k += 32) s += g_h[b*256 + k] * Wo[k];
    #pragma unroll
    for (int off = 16; off; off >>= 1) s += __shfl_down_sync(0xffffffffu, s, off);
    if (lane == 0) out[b] = fmaxf(s + bo[0], 0.f);
}

// ---------------------------------------------------------------------------
extern "C" void kernel_launch(void* const* d_in, const int* in_sizes, int n_in,
                              void* d_out, int out_size)
{
    const float* motion = (const float*)d_in[0];
    const float* robot  = (const float*)d_in[1];
    const float* osr    = (const float*)d_in[2];
    const float* osi    = (const float*)d_in[3];
    const float* hist   = (const float*)d_in[4];
    const float* act    = (const float*)d_in[5];
    const float* orr_   = (const float*)d_in[6];
    const float* ori_   = (const float*)d_in[7];
    const float* Wm  = (const float*)d_in[8];
    const float* bm  = (const float*)d_in[9];
    const float* Wr  = (const float*)d_in[10];
    const float* br  = (const float*)d_in[11];
    const float* Wre = (const float*)d_in[12];
    const float* bre = (const float*)d_in[13];
    const float* Wim = (const float*)d_in[14];
    const float* bim = (const float*)d_in[15];
    const float* Wc  = (const float*)d_in[16];
    const float* bc  = (const float*)d_in[17];
    const float* Wk  = (const float*)d_in[18];
    const float* Wrk = (const float*)d_in[19];
    const float* bl  = (const float*)d_in[20];
    const float* Wo  = (const float*)d_in[21];
    const float* bo  = (const float*)d_in[22];
    float* out = (float*)d_out;

    reformat_wrk<<<256, 256>>>(Wrk);

    preamble_kernel<<<BATCH, 256>>>(motion, robot, osr, osi, orr_, ori_,
                                    Wm, bm, Wr, br, Wre, bre, Wim, bim, Wc, bc);

    dim3 g2(G4 / 128, (TSTEPS * BATCH) / 128);   // (8, 1020)
    xwk_kernel<<<g2, 256>>>(hist, act, Wk, bl);

    recur_kernel<<<RCTAS, 256>>>();

    out_kernel<<<BATCH, 32>>>(Wo, bo, out);
}

// round 3
// speedup vs baseline: 1.5717x; 1.0606x over previous
#include <cuda_runtime.h>
#include <math.h>

#define BATCH   512
#define STEPS   128
#define TSTEPS  255          // 127 history + 128 action
#define DIN     256
#define UDIM    256
#define G4      1024         // 4*UDIM
#define RROWS   6            // batch rows per recurrence CTA
#define RCTAS   ((BATCH + RROWS - 1) / RROWS)   // 86

// Scratch (static device allocations — no cudaMalloc anywhere)
__device__ float  g_state[BATCH * UDIM];
__device__ float  g_h[BATCH * UDIM];
__device__ float  g_G[(size_t)TSTEPS * BATCH * G4];   // 535 MB: x@Wk + bl, [t][b][4U]
__device__ float4 g_W4[256 * 256];                    // Wrk reformat: (wi,wf,wg,wo) per (k,n)

// ---------------------------------------------------------------------------
// f32x2 packed-FMA helpers (sm_103a FFMA2 — only reachable via PTX)
// ---------------------------------------------------------------------------
union F2U { float2 f; unsigned long long u; };
union F4U { float4 f; ulonglong2 u; };

__device__ __forceinline__ void fma2(unsigned long long& d,
                                     unsigned long long a,
                                     unsigned long long b)
{
    asm("fma.rn.f32x2 %0, %1, %2, %0;" : "+l"(d) : "l"(a), "l"(b));
}
__device__ __forceinline__ unsigned long long dup2(float x)
{
    F2U t; t.f = make_float2(x, x); return t.u;
}
__device__ __forceinline__ float tanha(float x)
{
    float y; asm("tanh.approx.f32 %0, %1;" : "=f"(y) : "f"(x)); return y;
}
__device__ __forceinline__ float sigm(float x)
{
    return fmaf(0.5f, tanha(0.5f * x), 0.5f);
}

// ---------------------------------------------------------------------------
// K0: reformat Wrk [256,1024] -> W4[k][n] = (W[k][n], W[k][256+n], W[k][512+n], W[k][768+n])
// ---------------------------------------------------------------------------
__global__ void reformat_wrk(const float* __restrict__ Wrk)
{
    const int idx = blockIdx.x * 256 + threadIdx.x;   // 65536
    const int k = idx >> 8, n = idx & 255;
    const float* w = Wrk + k * G4 + n;
    g_W4[idx] = make_float4(w[0], w[256], w[512], w[768]);
}

// ---------------------------------------------------------------------------
// K1: preamble — ms/rs/re/im + combine -> state [512,256]
// ---------------------------------------------------------------------------
__global__ void __launch_bounds__(256) preamble_kernel(
    const float* __restrict__ motion, const float* __restrict__ robot,
    const float* __restrict__ osr,    const float* __restrict__ osi,
    const float* __restrict__ orr_,   const float* __restrict__ ori_,
    const float* __restrict__ Wm, const float* __restrict__ bm,
    const float* __restrict__ Wr, const float* __restrict__ br,
    const float* __restrict__ Wre, const float* __restrict__ bre,
    const float* __restrict__ Wim, const float* __restrict__ bim,
    const float* __restrict__ Wc,  const float* __restrict__ bc)
{
    __shared__ float comb[768];
    const int row = blockIdx.x;
    const int n   = threadIdx.x;

    float s = bm[n];
    #pragma unroll 8
    for (int k = 0; k < 64; k++) s += motion[row*64 + k] * Wm[k*256 + n];
    comb[n] = fmaxf(s, 0.f);

    s = br[n];
    #pragma unroll 8
    for (int k = 0; k < 128; k++) s += robot[row*128 + k] * Wr[k*256 + n];
    comb[256 + n] = fmaxf(s, 0.f);

    if (n < 128) {
        float s3 = bre[n];
        #pragma unroll 8
        for (int k = 0; k < 64; k++) s3 += osr [row*64 + k] * Wre[k*128 + n];
        #pragma unroll 8
        for (int k = 0; k < 64; k++) s3 += orr_[row*64 + k] * Wre[(64+k)*128 + n];
        comb[512 + n] = fmaxf(s3, 0.f);
    } else {
        const int m = n - 128;
        float s4 = bim[m];
        #pragma unroll 8
        for (int k = 0; k < 64; k++) s4 += osi [row*64 + k] * Wim[k*128 + m];
        #pragma unroll 8
        for (int k = 0; k < 64; k++) s4 += ori_[row*64 + k] * Wim[(64+k)*128 + m];
        comb[640 + m] = fmaxf(s4, 0.f);
    }
    __syncthreads();

    float s5 = bc[n];
    #pragma unroll 8
    for (int k = 0; k < 768; k++) s5 += comb[k] * Wc[k*256 + n];
    g_state[row*256 + n] = fmaxf(s5, 0.f);
}

// ---------------------------------------------------------------------------
// K2: G = x @ Wk + bl.  M=130560, K=256, N=1024.
// 128x128 tile, BK=16, 256 threads, 8x8 microtile, FFMA2, reg-prefetch.
// ---------------------------------------------------------------------------
__global__ void __launch_bounds__(256, 1) xwk_kernel(
    const float* __restrict__ hist, const float* __restrict__ act,
    const float* __restrict__ Wk,   const float* __restrict__ bl)
{
    __shared__ float As[16][132];   // [k][m], padded
    __shared__ float Bs[16][128];   // [k][n]

    const int tid = threadIdx.x;
    const int tx  = tid & 15, ty = tid >> 4;
    const int bm0 = blockIdx.y * 128;
    const int bn0 = blockIdx.x * 128;

    const int ra = tid >> 2;              // 0..63
    const int kc = (tid & 3) * 4;         // 0,4,8,12
    const int mA0 = bm0 + ra, mA1 = bm0 + ra + 64;
    const int tA0 = mA0 >> 9, bA0 = mA0 & 511;
    const int tA1 = mA1 >> 9, bA1 = mA1 & 511;
    const float* arow0 = (tA0 < 127)
        ? (hist + ((size_t)bA0 * STEPS + tA0) * DIN)
        : (act  + ((size_t)bA0 * STEPS + (tA0 - 127)) * DIN);
    const float* arow1 = (tA1 < 127)
        ? (hist + ((size_t)bA1 * STEPS + tA1) * DIN)
        : (act  + ((size_t)bA1 * STEPS + (tA1 - 127)) * DIN);

    const int kb = tid >> 4;              // 0..15
    const int nb = (tid & 15) * 4;        // 0..60
    const float* bsrc = Wk + (size_t)kb * G4 + bn0 + nb;

    unsigned long long acc[8][4];
    #pragma unroll
    for (int i = 0; i < 8; i++)
        #pragma unroll
        for (int j = 0; j < 4; j++) acc[i][j] = 0ull;

    float4 a0 = *(const float4*)(arow0 + kc);
    float4 a1 = *(const float4*)(arow1 + kc);
    float4 b0 = *(const float4*)(bsrc);
    float4 b1 = *(const float4*)(bsrc + 64);

    for (int k0 = 0; k0 < 256; k0 += 16) {
        __syncthreads();
        As[kc+0][ra] = a0.x; As[kc+1][ra] = a0.y; As[kc+2][ra] = a0.z; As[kc+3][ra] = a0.w;
        As[kc+0][ra+64] = a1.x; As[kc+1][ra+64] = a1.y; As[kc+2][ra+64] = a1.z; As[kc+3][ra+64] = a1.w;
        *(float4*)&Bs[kb][nb]      = b0;
        *(float4*)&Bs[kb][nb + 64] = b1;
        __syncthreads();

        if (k0 + 16 < 256) {
            a0 = *(const float4*)(arow0 + k0 + 16 + kc);
            a1 = *(const float4*)(arow1 + k0 + 16 + kc);
            b0 = *(const float4*)(bsrc + (size_t)(k0 + 16) * G4);
            b1 = *(const float4*)(bsrc + (size_t)(k0 + 16) * G4 + 64);
        }

        #pragma unroll
        for (int k = 0; k < 16; k++) {
            float4 av0 = *(const float4*)&As[k][ty*8];
            float4 av1 = *(const float4*)&As[k][ty*8 + 4];
            F4U bv0, bv1;
            bv0.f = *(const float4*)&Bs[k][tx*8];
            bv1.f = *(const float4*)&Bs[k][tx*8 + 4];
            unsigned long long bp[4] = { bv0.u.x, bv0.u.y, bv1.u.x, bv1.u.y };
            float afl[8] = { av0.x, av0.y, av0.z, av0.w, av1.x, av1.y, av1.z, av1.w };
            #pragma unroll
            for (int i = 0; i < 8; i++) {
                unsigned long long ad = dup2(afl[i]);
                #pragma unroll
                for (int j = 0; j < 4; j++) fma2(acc[i][j], ad, bp[j]);
            }
        }
    }

    float blv[8];
    #pragma unroll
    for (int j = 0; j < 8; j++) blv[j] = bl[bn0 + tx*8 + j];

    #pragma unroll
    for (int i = 0; i < 8; i++) {
        const int m = bm0 + ty*8 + i;
        float v[8];
        #pragma unroll
        for (int j = 0; j < 4; j++) {
            F2U e; e.u = acc[i][j];
            v[j*2]   = e.f.x + blv[j*2];
            v[j*2+1] = e.f.y + blv[j*2+1];
        }
        float* dst = g_G + (size_t)m * G4 + bn0 + tx*8;
        *(float4*)dst       = make_float4(v[0], v[1], v[2], v[3]);
        *(float4*)(dst + 4) = make_float4(v[4], v[5], v[6], v[7]);
    }
}

// ---------------------------------------------------------------------------
// K3: persistent LSTM recurrence. 86 CTAs x 6 batch rows, 512 threads.
// K-split: warps 0-7 handle k in [0,128), warps 8-15 handle k in [128,256).
// Partial accumulators reduced through smem each step. h kept duplicated
// (float2) in smem; LDS.128 fetches two k's per load. W4 gate-interleaved
// float4 -> 1 LDG.128 per (k, feature).
// ---------------------------------------------------------------------------
__global__ void __launch_bounds__(512, 1) recur_kernel()
{
    __shared__ float2 hs2[RROWS][256];        // 12 KB, h duplicated
    __shared__ float4 part[RROWS][256];       // 24 KB, (if.x, if.y, go.x, go.y) partials

    const int tid  = threadIdx.x;
    const int n    = tid & 255;               // gate feature
    const int half = tid >> 8;                // k half: 0 or 1
    const int r0   = blockIdx.x * RROWS;

    int gr[RROWS];
    #pragma unroll
    for (int r = 0; r < RROWS; r++) gr[r] = min(r0 + r, BATCH - 1);

    float c[RROWS];
    if (half == 0) {
        #pragma unroll
        for (int r = 0; r < RROWS; r++) {
            c[r] = g_state[gr[r] * 256 + n];
            hs2[r][n] = make_float2(c[r], c[r]);
        }
    }
    __syncthreads();

    const float4* wp = g_W4 + (size_t)(half * 128) * 256 + n;
    const int kbase = half * 128;

    for (int t = 0; t < TSTEPS; t++) {
        // hoist G loads (half 0 only) — they land under the k-loop
        float gz[RROWS][4];
        if (half == 0) {
            #pragma unroll
            for (int r = 0; r < RROWS; r++) {
                const float* Gp = g_G + ((size_t)t * BATCH + gr[r]) * G4 + n;
                gz[r][0] = Gp[0];   gz[r][1] = Gp[256];
                gz[r][2] = Gp[512]; gz[r][3] = Gp[768];
            }
        }

        unsigned long long accif[RROWS], accgo[RROWS];
        #pragma unroll
        for (int r = 0; r < RROWS; r++) { accif[r] = 0ull; accgo[r] = 0ull; }

        #pragma unroll 4
        for (int k2 = 0; k2 < 128; k2 += 2) {
            F4U w0, w1;
            w0.f = wp[(size_t)k2 * 256];
            w1.f = wp[(size_t)(k2 + 1) * 256];
            #pragma unroll
            for (int r = 0; r < RROWS; r++) {
                F4U hh; hh.f = *(const float4*)&hs2[r][kbase + k2];
                fma2(accif[r], w0.u.x, hh.u.x);
                fma2(accgo[r], w0.u.y, hh.u.x);
                fma2(accif[r], w1.u.x, hh.u.y);
                fma2(accgo[r], w1.u.y, hh.u.y);
            }
        }

        if (half == 1) {
            #pragma unroll
            for (int r = 0; r < RROWS; r++) {
                F4U p; p.u.x = accif[r]; p.u.y = accgo[r];
                part[r][n] = p.f;
            }
        }
        __syncthreads();   // partials visible; all hs2 reads complete

        if (half == 0) {
            #pragma unroll
            for (int r = 0; r < RROWS; r++) {
                F4U p; p.f = part[r][n];
                F2U eif, ego; eif.u = accif[r]; ego.u = accgo[r];
                const float zi = eif.f.x + p.f.x + gz[r][0];
                const float zf = eif.f.y + p.f.y + gz[r][1];
                const float zg = ego.f.x + p.f.z + gz[r][2];
                const float zo = ego.f.y + p.f.w + gz[r][3];
                const float ig = sigm(zi);
                const float fg = sigm(zf);
                const float gg = tanha(zg);
                const float og = sigm(zo);
                c[r] = fg * c[r] + ig * gg;
                const float h = og * tanha(c[r]);
                hs2[r][n] = make_float2(h, h);
            }
        }
        __syncthreads();   // new h (and freed part) visible to all
    }

    if (half == 0) {
        #pragma unroll
        for (int r = 0; r < RROWS; r++)
            if (r0 + r < BATCH) g_h[(r0 + r) * 256 + n] = hs2[r][n].x;
    }
}

// ---------------------------------------------------------------------------
// K4: out = relu(h @ Wo + bo), [512,1]. One warp per batch row.
// ---------------------------------------------------------------------------
__global__ void out_kernel(const float* __restrict__ Wo,
                           const float* __restrict__ bo,
                           float* __restrict__ out)
{
    const int b = blockIdx.x;
    const int lane = threadIdx.x;
    float s = 0.f;
    #pragma unroll
    for (int k = lane; k < 256; k += 32) s += g_h[b*256 + k] * Wo[k];
    #pragma unroll
    for (int off = 16; off; off >>= 1) s += __shfl_down_sync(0xffffffffu, s, off);
    if (lane == 0) out[b] = fmaxf(s + bo[0], 0.f);
}

// ---------------------------------------------------------------------------
extern "C" void kernel_launch(void* const* d_in, const int* in_sizes, int n_in,
                              void* d_out, int out_size)
{
    const float* motion = (const float*)d_in[0];
    const float* robot  = (const float*)d_in[1];
    const float* osr    = (const float*)d_in[2];
    const float* osi    = (const float*)d_in[3];
    const float* hist   = (const float*)d_in[4];
    const float* act    = (const float*)d_in[5];
    const float* orr_   = (const float*)d_in[6];
    const float* ori_   = (const float*)d_in[7];
    const float* Wm  = (const float*)d_in[8];
    const float* bm  = (const float*)d_in[9];
    const float* Wr  = (const float*)d_in[10];
    const float* br  = (const float*)d_in[11];
    const float* Wre = (const float*)d_in[12];
    const float* bre = (const float*)d_in[13];
    const float* Wim = (const float*)d_in[14];
    const float* bim = (const float*)d_in[15];
    const float* Wc  = (const float*)d_in[16];
    const float* bc  = (const float*)d_in[17];
    const float* Wk  = (const float*)d_in[18];
    const float* Wrk = (const float*)d_in[19];
    const float* bl  = (const float*)d_in[20];
    const float* Wo  = (const float*)d_in[21];
    const float* bo  = (const float*)d_in[22];
    float* out = (float*)d_out;

    reformat_wrk<<<256, 256>>>(Wrk);

    preamble_kernel<<<BATCH, 256>>>(motion, robot, osr, osi, orr_, ori_,
                                    Wm, bm, Wr, br, Wre, bre, Wim, bim, Wc, bc);

    dim3 g2(G4 / 128, (TSTEPS * BATCH) / 128);   // (8, 1020)
    xwk_kernel<<<g2, 256>>>(hist, act, Wk, bl);

    recur_kernel<<<RCTAS, 512>>>();

    out_kernel<<<BATCH, 32>>>(Wo, bo, out);
}